// round 6
// baseline (speedup 1.0000x reference)
#include <cuda_runtime.h>
#include <cuda_bf16.h>

#define N_NODES 50000
#define N_EDGES 800000
#define D 64
#define SCAN_BLK 1024
#define SCAN_NB  ((N_NODES + 1 + SCAN_BLK - 1) / SCAN_BLK)   // 49

// Packed fp32x2 FMA (Blackwell FFMA2; ptxas won't emit it from plain C++).
#define FMA_F32X2(d, a, bb, c) \
    asm("fma.rn.f32x2 %0, %1, %2, %3;" : "=l"(d) : "l"(a), "l"(bb), "l"(c))
#define PACK2(dst, lo, hi) \
    asm("mov.b64 %0, {%1, %2};" : "=l"(dst) : "f"(lo), "f"(hi))
#define UNPACK2(lo, hi, srcv) \
    asm("mov.b64 {%0, %1}, %2;" : "=f"(lo), "=f"(hi) : "l"(srcv))

// ---- device-global scratch (no allocations allowed) ----
// Invariant at every kernel_launch entry: g_count == 0 and g_scan_flag == 0
// (BSS-zero initially; reset-after-consume inside the pipeline each call).
__device__ int   g_count[N_NODES];
__device__ int   g_off[N_NODES + 1];
__device__ int   g_cursor[N_NODES];
__device__ __align__(16) float g_exp_s[N_EDGES];
__device__ __align__(16) int2  g_perm[N_EDGES];      // (src, ex-bits)
__device__ __align__(16) float g_hsum[N_NODES * D];  // normalized aggregation
__device__ volatile int g_scan_tot[SCAN_NB];
__device__ volatile int g_scan_flag[SCAN_NB];

// ---------------------------------------------------------------------------
// K1: streaming score pass. Half-warp (16 lanes x float4) per edge:
//   exp_s[edge] = exp(dot(h_src[src], e));  count[dst]++ (degree histogram)
// e is read SEQUENTIALLY (full DRAM bandwidth); h_src gathered from L2.
// ---------------------------------------------------------------------------
__global__ void kgcn_score_kernel(const float* __restrict__ h_src,
                                  const float* __restrict__ e,
                                  const int* __restrict__ src,
                                  const int* __restrict__ dst) {
    int tid  = blockIdx.x * blockDim.x + threadIdx.x;
    int edge = tid >> 4;
    int sub  = tid & 15;
    if (edge >= N_EDGES) return;   // never taken: E*16 == grid exactly

    int s = src[edge];
    float4 hv = reinterpret_cast<const float4*>(h_src)[(size_t)s * 16 + sub];
    float4 ev = reinterpret_cast<const float4*>(e)[(size_t)edge * 16 + sub];

    float dot = hv.x * ev.x + hv.y * ev.y + hv.z * ev.z + hv.w * ev.w;
    dot += __shfl_xor_sync(0xffffffffu, dot, 1);
    dot += __shfl_xor_sync(0xffffffffu, dot, 2);
    dot += __shfl_xor_sync(0xffffffffu, dot, 4);
    dot += __shfl_xor_sync(0xffffffffu, dot, 8);

    if (sub == 0) {
        g_exp_s[edge] = __expf(dot);
        atomicAdd(&g_count[dst[edge]], 1);
    }
}

// ---------------------------------------------------------------------------
// K2: single-kernel exclusive scan (decoupled lookback, 49 wave-1-resident
// blocks). Sets g_off / g_cursor, resets g_count for the next call.
// ---------------------------------------------------------------------------
__global__ void __launch_bounds__(SCAN_BLK) kgcn_scan_kernel() {
    __shared__ int wsum[32];
    __shared__ int s_prefix;
    const int tid = threadIdx.x, b = blockIdx.x;
    const int i = b * SCAN_BLK + tid;

    int v = (i < N_NODES) ? g_count[i] : 0;

    int lane = tid & 31, wid = tid >> 5;
    int x = v;
    #pragma unroll
    for (int dd = 1; dd < 32; dd <<= 1) {
        int y = __shfl_up_sync(0xffffffffu, x, dd);
        if (lane >= dd) x += y;
    }
    if (lane == 31) wsum[wid] = x;
    __syncthreads();
    if (wid == 0) {
        int s = wsum[lane];
        #pragma unroll
        for (int dd = 1; dd < 32; dd <<= 1) {
            int y = __shfl_up_sync(0xffffffffu, s, dd);
            if (lane >= dd) s += y;
        }
        wsum[lane] = s;
    }
    __syncthreads();
    int incl = x + ((wid > 0) ? wsum[wid - 1] : 0);

    if (tid == SCAN_BLK - 1) {
        g_scan_tot[b] = incl;
        __threadfence();
        g_scan_flag[b] = 1;
    }

    if (tid < 32) {
        int sum = 0;
        for (int j = tid; j < b; j += 32) {
            while (g_scan_flag[j] == 0) { }
            sum += g_scan_tot[j];
        }
        #pragma unroll
        for (int o = 16; o; o >>= 1) sum += __shfl_xor_sync(0xffffffffu, sum, o);
        if (tid == 0) s_prefix = sum;
    }
    __syncthreads();

    int off = s_prefix + incl - v;
    if (i <= N_NODES) {
        g_off[i] = off;
        if (i < N_NODES) {
            g_cursor[i] = off;
            g_count[i] = 0;           // reset-after-consume
        }
    }
}

// ---------------------------------------------------------------------------
// K3: scatter CSR records with ex BAKED IN: perm[pos] = (src, bits(exp_s[e])).
// Also resets the scan flags for the next call.
// ---------------------------------------------------------------------------
__global__ void kgcn_scatter_kernel(const int* __restrict__ src,
                                    const int* __restrict__ dst) {
    int e = blockIdx.x * blockDim.x + threadIdx.x;
    if (e < SCAN_NB) g_scan_flag[e] = 0;              // reset-after-consume
    if (e >= N_EDGES) return;
    int d = dst[e];
    int pos = atomicAdd(&g_cursor[d], 1);
    g_perm[pos] = make_int2(src[e], __float_as_int(g_exp_s[e]));
}

// ---------------------------------------------------------------------------
// K4: pull-aggregate. 16 lanes per node; record gives (src, ex) directly —
// NO e reads, NO shfl, NO expf. Unrolled 2-wide for load MLP. Register
// accumulation, one normalized write. No atomics.
// ---------------------------------------------------------------------------
__global__ void kgcn_pull_kernel(const float* __restrict__ h_src) {
    int tid  = blockIdx.x * blockDim.x + threadIdx.x;
    int node = tid >> 4;
    int sub  = tid & 15;
    if (node >= N_NODES) return;   // never taken: N*16 == grid exactly

    int beg = g_off[node];
    int end = g_off[node + 1];

    const float4* h4 = reinterpret_cast<const float4*>(h_src);
    float4 acc = make_float4(0.f, 0.f, 0.f, 0.f);
    float den = 0.f;

    int i = beg;
    for (; i + 1 < end; i += 2) {
        int2 a = g_perm[i];
        int2 c = g_perm[i + 1];
        float4 h0 = h4[(size_t)a.x * 16 + sub];
        float4 h1 = h4[(size_t)c.x * 16 + sub];
        float e0 = __int_as_float(a.y);
        float e1 = __int_as_float(c.y);
        den += e0 + e1;
        acc.x = fmaf(e0, h0.x, acc.x); acc.y = fmaf(e0, h0.y, acc.y);
        acc.z = fmaf(e0, h0.z, acc.z); acc.w = fmaf(e0, h0.w, acc.w);
        acc.x = fmaf(e1, h1.x, acc.x); acc.y = fmaf(e1, h1.y, acc.y);
        acc.z = fmaf(e1, h1.z, acc.z); acc.w = fmaf(e1, h1.w, acc.w);
    }
    if (i < end) {
        int2 a = g_perm[i];
        float4 h0 = h4[(size_t)a.x * 16 + sub];
        float e0 = __int_as_float(a.y);
        den += e0;
        acc.x = fmaf(e0, h0.x, acc.x); acc.y = fmaf(e0, h0.y, acc.y);
        acc.z = fmaf(e0, h0.z, acc.z); acc.w = fmaf(e0, h0.w, acc.w);
    }

    float inv = (den > 0.f) ? (1.0f / den) : 0.f;   // degree-0 node -> 0
    reinterpret_cast<float4*>(g_hsum)[(size_t)node * 16 + sub] =
        make_float4(acc.x * inv, acc.y * inv, acc.z * inv, acc.w * inv);
}

// ---------------------------------------------------------------------------
// K5: out = concat(h_dst, h_sum) @ W^T + b
// 64-node x 64-col tile, 256 threads (4 nodes x 4 cols each).
// h_s stored [k][node] so the 4-node read is one LDS128 (broadcast across
// half-warps); inner loop = 2xLDS128 + 8 FFMA2 per k (packed f32x2 doubles
// FMA throughput vs FFMA's rt=2 floor).
// ---------------------------------------------------------------------------
#define HT_STRIDE 68   // 64 + 4 pad; keeps float4 alignment (68*4 % 16 == 0)
__global__ void __launch_bounds__(256) kgcn_out_kernel(
        const float* __restrict__ h_dst,
        const float* __restrict__ W,
        const float* __restrict__ b,
        float* __restrict__ out) {
    __shared__ float W_s[128 * 64];            // [k][j] transposed, 32KB
    __shared__ float h_s[32 * HT_STRIDE];      // [kk][node], padded

    const int tid = threadIdx.x;
    for (int i = tid; i < 64 * 128; i += 256) {
        int j = i >> 7;     // out col
        int k = i & 127;    // in  idx
        W_s[k * 64 + j] = W[i];
    }

    const int tx = tid & 15;      // cols 4*tx..4*tx+3
    const int ty = tid >> 4;      // nodes 4*ty..4*ty+3
    const int node0 = blockIdx.x * 64;

    unsigned long long acc01[4], acc23[4];     // packed (col pair) per node
    #pragma unroll
    for (int n = 0; n < 4; n++) { acc01[n] = 0ull; acc23[n] = 0ull; }

    #pragma unroll
    for (int c = 0; c < 4; c++) {
        const float* srcp = (c < 2) ? h_dst : g_hsum;
        const int kof4 = (c & 1) * 8;

        __syncthreads();
        // Stage 64 nodes x 32 k-values, TRANSPOSED into h_s[kk][node].
        #pragma unroll
        for (int r = 0; r < 2; r++) {
            int idx = tid + r * 256;    // 0..511
            int n   = idx >> 3;         // local node 0..63
            int q   = idx & 7;          // float4 slot
            int gn  = node0 + n;
            float4 v = make_float4(0.f, 0.f, 0.f, 0.f);
            if (gn < N_NODES)
                v = reinterpret_cast<const float4*>(srcp)[(size_t)gn * 16 + kof4 + q];
            h_s[(q * 4 + 0) * HT_STRIDE + n] = v.x;
            h_s[(q * 4 + 1) * HT_STRIDE + n] = v.y;
            h_s[(q * 4 + 2) * HT_STRIDE + n] = v.z;
            h_s[(q * 4 + 3) * HT_STRIDE + n] = v.w;
        }
        __syncthreads();

        const float* Wrow = &W_s[(c * 32) * 64 + 4 * tx];
        #pragma unroll 8
        for (int kk = 0; kk < 32; kk++) {
            float4 w = *reinterpret_cast<const float4*>(Wrow + kk * 64);
            unsigned long long w01, w23;
            PACK2(w01, w.x, w.y);
            PACK2(w23, w.z, w.w);
            float4 h = *reinterpret_cast<const float4*>(&h_s[kk * HT_STRIDE + 4 * ty]);
            #pragma unroll
            for (int n = 0; n < 4; n++) {
                float hn = (n == 0) ? h.x : (n == 1) ? h.y : (n == 2) ? h.z : h.w;
                unsigned long long hh;
                PACK2(hh, hn, hn);
                FMA_F32X2(acc01[n], hh, w01, acc01[n]);
                FMA_F32X2(acc23[n], hh, w23, acc23[n]);
            }
        }
    }

    float4 bb = *reinterpret_cast<const float4*>(&b[4 * tx]);
    #pragma unroll
    for (int n = 0; n < 4; n++) {
        int gn = node0 + 4 * ty + n;
        if (gn < N_NODES) {
            float a0, a1, a2, a3;
            UNPACK2(a0, a1, acc01[n]);
            UNPACK2(a2, a3, acc23[n]);
            float4 o = make_float4(a0 + bb.x, a1 + bb.y, a2 + bb.z, a3 + bb.w);
            reinterpret_cast<float4*>(out)[(size_t)gn * 16 + tx] = o;
        }
    }
}

// ---------------------------------------------------------------------------
// Launch.  Inputs: 0 h_src, 1 h_dst, 2 e, 3 src, 4 dst, 5 W, 6 b
// ---------------------------------------------------------------------------
extern "C" void kernel_launch(void* const* d_in, const int* in_sizes, int n_in,
                              void* d_out, int out_size) {
    const float* h_src = (const float*)d_in[0];
    const float* h_dst = (const float*)d_in[1];
    const float* e     = (const float*)d_in[2];
    const int*   src   = (const int*)d_in[3];
    const int*   dst   = (const int*)d_in[4];
    const float* W     = (const float*)d_in[5];
    const float* b     = (const float*)d_in[6];
    float* out = (float*)d_out;

    kgcn_score_kernel<<<50000, 256>>>(h_src, e, src, dst);  // 16 thr/edge
    kgcn_scan_kernel<<<SCAN_NB, SCAN_BLK>>>();
    kgcn_scatter_kernel<<<(N_EDGES + 255) / 256, 256>>>(src, dst);
    kgcn_pull_kernel<<<(N_NODES * 16) / 256, 256>>>(h_src); // 16 thr/node
    kgcn_out_kernel<<<(N_NODES + 63) / 64, 256>>>(h_dst, W, b, out);
}